// round 2
// baseline (speedup 1.0000x reference)
#include <cuda_runtime.h>

#define HW 36864
#define Cc 256
#define QKV_STRIDE 18874368   // 1152*16*64*16
#define ATTN_ELEMS 75497472   // 1152*16*64*64
#define AVG_ELEMS  73728      // 1152*64

__device__ __align__(16) float g_scratch[2 * QKV_STRIDE];   // q then k: [qkv][win][head][n][d]

// ---------------- fused 1x1conv + BN + ReLU + window rearrange ----------------
// GEMM: out[o, p] = sum_c W[o,c] * X[b,c,p]   (M=512 o, N=73728 p, K=256)
// Block tile 128(o) x 128(p), K-step 16, 256 threads, 8x8 micro-tile (split 2x2 of 4x4).
__global__ __launch_bounds__(256) void proj_kernel(
    const float* __restrict__ x, const float* __restrict__ w,
    const float* __restrict__ gamma, const float* __restrict__ beta,
    const float* __restrict__ rmean, const float* __restrict__ rvar)
{
    __shared__ __align__(16) float Ws[16][132];   // [k][o], padded (132*4B = 16B multiple)
    __shared__ __align__(16) float Xs[16][128];   // [k][p]

    const int tid = threadIdx.x;
    const int p0  = blockIdx.x * 128;
    const int o0  = blockIdx.y * 128;
    const int b   = p0 / HW;            // tile never crosses batch (36864 % 128 == 0)
    const int pp0 = p0 - b * HW;
    const float* xb = x + (size_t)b * (Cc * HW);

    const int tx = tid & 15;   // o dim
    const int ty = tid >> 4;   // p dim

    float acc[8][8];
#pragma unroll
    for (int i = 0; i < 8; i++)
#pragma unroll
        for (int j = 0; j < 8; j++) acc[i][j] = 0.f;

    for (int c0 = 0; c0 < Cc; c0 += 16) {
        // W tile (128 o x 16 c), transposed into Ws[k][o]
#pragma unroll
        for (int l = 0; l < 2; l++) {
            int f = tid + l * 256;
            int o = f >> 2;
            int cg = f & 3;
            float4 v = *reinterpret_cast<const float4*>(&w[(o0 + o) * Cc + c0 + cg * 4]);
            Ws[cg*4+0][o] = v.x; Ws[cg*4+1][o] = v.y;
            Ws[cg*4+2][o] = v.z; Ws[cg*4+3][o] = v.w;
        }
        // X tile (16 c x 128 p), rows contiguous in p -> coalesced float4
#pragma unroll
        for (int l = 0; l < 2; l++) {
            int f = tid + l * 256;
            int r = f >> 5;
            int c4 = f & 31;
            float4 v = *reinterpret_cast<const float4*>(&xb[(c0 + r) * HW + pp0 + c4 * 4]);
            *reinterpret_cast<float4*>(&Xs[r][c4*4]) = v;
        }
        __syncthreads();
#pragma unroll
        for (int kk = 0; kk < 16; kk++) {
            float a[8], bb[8];
            *reinterpret_cast<float4*>(&a[0])  = *reinterpret_cast<float4*>(&Ws[kk][tx*4]);
            *reinterpret_cast<float4*>(&a[4])  = *reinterpret_cast<float4*>(&Ws[kk][64+tx*4]);
            *reinterpret_cast<float4*>(&bb[0]) = *reinterpret_cast<float4*>(&Xs[kk][ty*4]);
            *reinterpret_cast<float4*>(&bb[4]) = *reinterpret_cast<float4*>(&Xs[kk][64+ty*4]);
#pragma unroll
            for (int i = 0; i < 8; i++)
#pragma unroll
                for (int j = 0; j < 8; j++)
                    acc[i][j] += a[i] * bb[j];
        }
        __syncthreads();
    }

    // epilogue: BN + ReLU + scatter to [qkv][win][head][n][d]
    int winv[8], nv[8];
#pragma unroll
    for (int hp = 0; hp < 2; hp++)
#pragma unroll
        for (int j = 0; j < 4; j++) {
            int pl = hp*64 + ty*4 + j;
            int pp = pp0 + pl;
            int row = pp / 192;
            int col = pp - row * 192;
            winv[hp*4+j] = b * 576 + (row >> 3) * 24 + (col >> 3);
            nv[hp*4+j]   = ((row & 7) << 3) + (col & 7);
        }
#pragma unroll
    for (int ho = 0; ho < 2; ho++) {
        int ob   = o0 + ho*64 + tx*4;      // 4 consecutive o, within one head (4-aligned)
        int qkv  = ob >> 8;
        int head = (ob >> 4) & 15;
        int dd0  = ob & 15;
        float inv[4], bz[4];
#pragma unroll
        for (int i = 0; i < 4; i++) {
            int og = ob + i;
            float iv = gamma[og] * rsqrtf(rvar[og] + 1e-5f);
            inv[i] = iv;
            bz[i]  = beta[og] - rmean[og] * iv;
        }
        float* basep = g_scratch + (size_t)qkv * QKV_STRIDE + head * 1024 + dd0;
#pragma unroll
        for (int hp = 0; hp < 2; hp++)
#pragma unroll
            for (int j = 0; j < 4; j++) {
                int pj = hp*4 + j;
                float4 v; float t;
                t = acc[ho*4+0][hp*4+j] * inv[0] + bz[0]; v.x = t > 0.f ? t : 0.f;
                t = acc[ho*4+1][hp*4+j] * inv[1] + bz[1]; v.y = t > 0.f ? t : 0.f;
                t = acc[ho*4+2][hp*4+j] * inv[2] + bz[2]; v.z = t > 0.f ? t : 0.f;
                t = acc[ho*4+3][hp*4+j] * inv[3] + bz[3]; v.w = t > 0.f ? t : 0.f;
                *reinterpret_cast<float4*>(basep + winv[pj]*16384 + nv[pj]*16) = v;
            }
    }
}

// ---------------- per-(window, head): dots + bias, avg colsum, softmax ----------------
__global__ __launch_bounds__(256) void attn_kernel(
    const float* __restrict__ rel_table,
    float* __restrict__ out_attn, float* __restrict__ out_avg)
{
    __shared__ __align__(16) float qs[1024];
    __shared__ __align__(16) float ks[1024];
    __shared__ __align__(16) float dots[64 * 68];   // padded stride 68 (68*4B = 16B mult)
    __shared__ float biash[225];                    // scalar-only access; keep LAST

    const int head = blockIdx.x;
    const int win  = blockIdx.y;
    const int tid  = threadIdx.x;

    const float* qg = g_scratch + win * 16384 + head * 1024;
    const float* kg = qg + QKV_STRIDE;
    *reinterpret_cast<float4*>(&qs[tid*4]) = *reinterpret_cast<const float4*>(&qg[tid*4]);
    *reinterpret_cast<float4*>(&ks[tid*4]) = *reinterpret_cast<const float4*>(&kg[tid*4]);
    if (tid < 225) biash[tid] = rel_table[tid * 16 + head];
    __syncthreads();

    const int n    = tid >> 2;   // query row, 4 threads per row
    const int part = tid & 3;    // 16 key columns each
    float qreg[16];
#pragma unroll
    for (int l = 0; l < 4; l++)
        *reinterpret_cast<float4*>(&qreg[l*4]) = *reinterpret_cast<float4*>(&qs[n*16 + l*4]);

    const int y1 = n >> 3, x1 = n & 7;
    float acc[16];
#pragma unroll
    for (int jj = 0; jj < 16; jj++) {
        int m = part * 16 + jj;
        float s = 0.f;
#pragma unroll
        for (int l = 0; l < 4; l++) {
            float4 kv = *reinterpret_cast<float4*>(&ks[m*16 + l*4]);
            s += qreg[l*4+0] * kv.x + qreg[l*4+1] * kv.y
               + qreg[l*4+2] * kv.z + qreg[l*4+3] * kv.w;
        }
        int y2 = m >> 3, x2 = m & 7;
        int r = (y1 - y2 + 7) * 15 + (x1 - x2 + 7);
        acc[jj] = s * 0.25f + biash[r];
        dots[n*68 + m] = acc[jj];     // pre-softmax for column sums
    }

    // row softmax: reduce across the 4 lanes of this row
    float mx = acc[0];
#pragma unroll
    for (int jj = 1; jj < 16; jj++) mx = fmaxf(mx, acc[jj]);
    mx = fmaxf(mx, __shfl_xor_sync(0xffffffffu, mx, 1));
    mx = fmaxf(mx, __shfl_xor_sync(0xffffffffu, mx, 2));
    float sum = 0.f;
#pragma unroll
    for (int jj = 0; jj < 16; jj++) { acc[jj] = __expf(acc[jj] - mx); sum += acc[jj]; }
    sum += __shfl_xor_sync(0xffffffffu, sum, 1);
    sum += __shfl_xor_sync(0xffffffffu, sum, 2);
    float rinv = __frcp_rn(sum);

    __syncthreads();   // all pre-softmax dots visible
    if (tid < 64) {
        float s = 0.f;
#pragma unroll
        for (int nn = 0; nn < 64; nn++) s += dots[nn*68 + tid];   // conflict-free (pad 4)
        atomicAdd(&out_avg[win * 64 + tid], s * (1.0f / 1024.0f));
    }
    __syncthreads();   // colsum readers done before overwrite
#pragma unroll
    for (int jj = 0; jj < 16; jj++)
        dots[n*68 + part*16 + jj] = acc[jj] * rinv;
    __syncthreads();

    // coalesced copy smem -> global
    float* ob = out_attn + (size_t)(win * 16 + head) * 4096;
#pragma unroll
    for (int l = 0; l < 4; l++) {
        int idx = tid + l * 256;       // float4 index, 1024 total
        int n2 = idx >> 4;
        int m4 = idx & 15;
        *reinterpret_cast<float4*>(&ob[idx*4]) =
            *reinterpret_cast<float4*>(&dots[n2*68 + m4*4]);
    }
}

extern "C" void kernel_launch(void* const* d_in, const int* in_sizes, int n_in,
                              void* d_out, int out_size) {
    const float* x     = (const float*)d_in[0];
    const float* w     = (const float*)d_in[1];
    const float* gamma = (const float*)d_in[2];
    const float* beta  = (const float*)d_in[3];
    const float* rmean = (const float*)d_in[4];
    const float* rvar  = (const float*)d_in[5];
    const float* rel   = (const float*)d_in[6];
    float* out     = (float*)d_out;
    float* out_avg = out + ATTN_ELEMS;

    cudaMemsetAsync(out_avg, 0, AVG_ELEMS * sizeof(float));
    proj_kernel<<<dim3(576, 4), 256>>>(x, w, gamma, beta, rmean, rvar);
    attn_kernel<<<dim3(16, 1152), 256>>>(rel, out, out_avg);
}

// round 3
// speedup vs baseline: 1.8195x; 1.8195x over previous
#include <cuda_runtime.h>

#define HW 36864
#define Cc 256
#define QKV_STRIDE 18874368   // 1152*16*64*16
#define ATTN_ELEMS 75497472   // 1152*16*64*64
#define AVG_ELEMS  73728      // 1152*64

__device__ __align__(16) float g_scratch[2 * QKV_STRIDE];   // q then k: [qkv][win][head][n][d]

// ---------------- fused 1x1conv + BN + ReLU + window rearrange ----------------
__global__ __launch_bounds__(256) void proj_kernel(
    const float* __restrict__ x, const float* __restrict__ w,
    const float* __restrict__ gamma, const float* __restrict__ beta,
    const float* __restrict__ rmean, const float* __restrict__ rvar)
{
    __shared__ __align__(16) float Ws[16][132];
    __shared__ __align__(16) float Xs[16][128];

    const int tid = threadIdx.x;
    const int p0  = blockIdx.x * 128;
    const int o0  = blockIdx.y * 128;
    const int b   = p0 / HW;
    const int pp0 = p0 - b * HW;
    const float* xb = x + (size_t)b * (Cc * HW);

    const int tx = tid & 15;
    const int ty = tid >> 4;

    float acc[8][8];
#pragma unroll
    for (int i = 0; i < 8; i++)
#pragma unroll
        for (int j = 0; j < 8; j++) acc[i][j] = 0.f;

    for (int c0 = 0; c0 < Cc; c0 += 16) {
#pragma unroll
        for (int l = 0; l < 2; l++) {
            int f = tid + l * 256;
            int o = f >> 2;
            int cg = f & 3;
            float4 v = *reinterpret_cast<const float4*>(&w[(o0 + o) * Cc + c0 + cg * 4]);
            Ws[cg*4+0][o] = v.x; Ws[cg*4+1][o] = v.y;
            Ws[cg*4+2][o] = v.z; Ws[cg*4+3][o] = v.w;
        }
#pragma unroll
        for (int l = 0; l < 2; l++) {
            int f = tid + l * 256;
            int r = f >> 5;
            int c4 = f & 31;
            float4 v = *reinterpret_cast<const float4*>(&xb[(c0 + r) * HW + pp0 + c4 * 4]);
            *reinterpret_cast<float4*>(&Xs[r][c4*4]) = v;
        }
        __syncthreads();
#pragma unroll
        for (int kk = 0; kk < 16; kk++) {
            float a[8], bb[8];
            *reinterpret_cast<float4*>(&a[0])  = *reinterpret_cast<float4*>(&Ws[kk][tx*4]);
            *reinterpret_cast<float4*>(&a[4])  = *reinterpret_cast<float4*>(&Ws[kk][64+tx*4]);
            *reinterpret_cast<float4*>(&bb[0]) = *reinterpret_cast<float4*>(&Xs[kk][ty*4]);
            *reinterpret_cast<float4*>(&bb[4]) = *reinterpret_cast<float4*>(&Xs[kk][64+ty*4]);
#pragma unroll
            for (int i = 0; i < 8; i++)
#pragma unroll
                for (int j = 0; j < 8; j++)
                    acc[i][j] += a[i] * bb[j];
        }
        __syncthreads();
    }

    int winv[8], nv[8];
#pragma unroll
    for (int hp = 0; hp < 2; hp++)
#pragma unroll
        for (int j = 0; j < 4; j++) {
            int pl = hp*64 + ty*4 + j;
            int pp = pp0 + pl;
            int row = pp / 192;
            int col = pp - row * 192;
            winv[hp*4+j] = b * 576 + (row >> 3) * 24 + (col >> 3);
            nv[hp*4+j]   = ((row & 7) << 3) + (col & 7);
        }
#pragma unroll
    for (int ho = 0; ho < 2; ho++) {
        int ob   = o0 + ho*64 + tx*4;
        int qkv  = ob >> 8;
        int head = (ob >> 4) & 15;
        int dd0  = ob & 15;
        float inv[4], bz[4];
#pragma unroll
        for (int i = 0; i < 4; i++) {
            int og = ob + i;
            float iv = gamma[og] * rsqrtf(rvar[og] + 1e-5f);
            inv[i] = iv;
            bz[i]  = beta[og] - rmean[og] * iv;
        }
        float* basep = g_scratch + (size_t)qkv * QKV_STRIDE + head * 1024 + dd0;
#pragma unroll
        for (int hp = 0; hp < 2; hp++)
#pragma unroll
            for (int j = 0; j < 4; j++) {
                int pj = hp*4 + j;
                float4 v; float t;
                t = acc[ho*4+0][hp*4+j] * inv[0] + bz[0]; v.x = t > 0.f ? t : 0.f;
                t = acc[ho*4+1][hp*4+j] * inv[1] + bz[1]; v.y = t > 0.f ? t : 0.f;
                t = acc[ho*4+2][hp*4+j] * inv[2] + bz[2]; v.z = t > 0.f ? t : 0.f;
                t = acc[ho*4+3][hp*4+j] * inv[3] + bz[3]; v.w = t > 0.f ? t : 0.f;
                *reinterpret_cast<float4*>(basep + winv[pj]*16384 + nv[pj]*16) = v;
            }
    }
}

// ---------------- attention: 4 (win,head) units per block, 64 thr/unit, 8x8 microtile ----
__global__ __launch_bounds__(256) void attn_kernel(
    const float* __restrict__ rel_table,
    float* __restrict__ out_attn, float* __restrict__ out_avg)
{
    __shared__ __align__(16) float qt[4][1024];   // [unit][d*64 + n]
    __shared__ __align__(16) float kt[4][1024];   // [unit][d*64 + m]
    __shared__ float biasu[4][226];

    const int tid  = threadIdx.x;
    const int u    = tid >> 6;
    const int t    = tid & 63;
    const int gu   = blockIdx.x * 4 + u;
    const int head = gu & 15;
    const int win  = gu >> 4;

    const float* qg = g_scratch + (size_t)win * 16384 + head * 1024;
    const float* kg = qg + QKV_STRIDE;

    // load q,k transposed into smem: qt[d][n]  (STS conflict-free: n = t contiguous)
#pragma unroll
    for (int d4 = 0; d4 < 4; d4++) {
        float4 v = *reinterpret_cast<const float4*>(&qg[t*16 + d4*4]);
        qt[u][(d4*4+0)*64 + t] = v.x;
        qt[u][(d4*4+1)*64 + t] = v.y;
        qt[u][(d4*4+2)*64 + t] = v.z;
        qt[u][(d4*4+3)*64 + t] = v.w;
        float4 kv = *reinterpret_cast<const float4*>(&kg[t*16 + d4*4]);
        kt[u][(d4*4+0)*64 + t] = kv.x;
        kt[u][(d4*4+1)*64 + t] = kv.y;
        kt[u][(d4*4+2)*64 + t] = kv.z;
        kt[u][(d4*4+3)*64 + t] = kv.w;
    }
    for (int idx = t; idx < 225; idx += 64)
        biasu[u][idx] = rel_table[idx * 16 + head];
    __syncthreads();

    const int cc = t & 7;    // col group: cols m = cc*8 + j
    const int rr = t >> 3;   // row group: rows n = rr*8 + i

    float acc[8][8];
#pragma unroll
    for (int i = 0; i < 8; i++)
#pragma unroll
        for (int j = 0; j < 8; j++) acc[i][j] = 0.f;

    const float* qb = &qt[u][rr * 8];
    const float* kb = &kt[u][cc * 8];
#pragma unroll
    for (int d = 0; d < 16; d++) {
        float a[8], bb[8];
        *reinterpret_cast<float4*>(&a[0])  = *reinterpret_cast<const float4*>(&qb[d*64]);
        *reinterpret_cast<float4*>(&a[4])  = *reinterpret_cast<const float4*>(&qb[d*64 + 4]);
        *reinterpret_cast<float4*>(&bb[0]) = *reinterpret_cast<const float4*>(&kb[d*64]);
        *reinterpret_cast<float4*>(&bb[4]) = *reinterpret_cast<const float4*>(&kb[d*64 + 4]);
#pragma unroll
        for (int i = 0; i < 8; i++)
#pragma unroll
            for (int j = 0; j < 8; j++)
                acc[i][j] += a[i] * bb[j];
    }

    // bias: rows y1=rr, x1=i; cols y2=cc, x2=j -> r = (rr-cc+7)*15 + (i-j+7)
    float b[15];
    {
        const float* bp = &biasu[u][(rr - cc + 7) * 15];
#pragma unroll
        for (int k = 0; k < 15; k++) b[k] = bp[k];
    }
#pragma unroll
    for (int i = 0; i < 8; i++)
#pragma unroll
        for (int j = 0; j < 8; j++)
            acc[i][j] = acc[i][j] * 0.25f + b[i - j + 7];

    // column sums (pre-softmax) -> avg. lanes: t&31 = (rr&3)*8 + cc
#pragma unroll
    for (int j = 0; j < 8; j++) {
        float s = acc[0][j] + acc[1][j] + acc[2][j] + acc[3][j]
                + acc[4][j] + acc[5][j] + acc[6][j] + acc[7][j];
        s += __shfl_xor_sync(0xffffffffu, s, 8);
        s += __shfl_xor_sync(0xffffffffu, s, 16);
        if ((t & 31) < 8)
            atomicAdd(&out_avg[win * 64 + cc * 8 + j], s * (1.0f / 1024.0f));
    }

    // row softmax: reduce over cc lanes (xor 1,2,4)
#pragma unroll
    for (int i = 0; i < 8; i++) {
        float mx = acc[i][0];
#pragma unroll
        for (int j = 1; j < 8; j++) mx = fmaxf(mx, acc[i][j]);
        mx = fmaxf(mx, __shfl_xor_sync(0xffffffffu, mx, 1));
        mx = fmaxf(mx, __shfl_xor_sync(0xffffffffu, mx, 2));
        mx = fmaxf(mx, __shfl_xor_sync(0xffffffffu, mx, 4));
        float sum = 0.f;
#pragma unroll
        for (int j = 0; j < 8; j++) { acc[i][j] = __expf(acc[i][j] - mx); sum += acc[i][j]; }
        sum += __shfl_xor_sync(0xffffffffu, sum, 1);
        sum += __shfl_xor_sync(0xffffffffu, sum, 2);
        sum += __shfl_xor_sync(0xffffffffu, sum, 4);
        float rinv = __frcp_rn(sum);
#pragma unroll
        for (int j = 0; j < 8; j++) acc[i][j] *= rinv;
    }

    // store from registers: rows rr*8+i, cols cc*8..cc*8+7
    float* ob = out_attn + ((size_t)(win * 16 + head) * 64 + rr * 8) * 64 + cc * 8;
#pragma unroll
    for (int i = 0; i < 8; i++) {
        float4 v0 = make_float4(acc[i][0], acc[i][1], acc[i][2], acc[i][3]);
        float4 v1 = make_float4(acc[i][4], acc[i][5], acc[i][6], acc[i][7]);
        *reinterpret_cast<float4*>(&ob[i * 64])     = v0;
        *reinterpret_cast<float4*>(&ob[i * 64 + 4]) = v1;
    }
}

extern "C" void kernel_launch(void* const* d_in, const int* in_sizes, int n_in,
                              void* d_out, int out_size) {
    const float* x     = (const float*)d_in[0];
    const float* w     = (const float*)d_in[1];
    const float* gamma = (const float*)d_in[2];
    const float* beta  = (const float*)d_in[3];
    const float* rmean = (const float*)d_in[4];
    const float* rvar  = (const float*)d_in[5];
    const float* rel   = (const float*)d_in[6];
    float* out     = (float*)d_out;
    float* out_avg = out + ATTN_ELEMS;

    cudaMemsetAsync(out_avg, 0, AVG_ELEMS * sizeof(float));
    proj_kernel<<<dim3(576, 4), 256>>>(x, w, gamma, beta, rmean, rvar);
    attn_kernel<<<4608, 256>>>(rel, out, out_avg);
}

// round 4
// speedup vs baseline: 3.3796x; 1.8574x over previous
#include <cuda_runtime.h>
#include <cstdint>

#define HW 36864
#define Cc 256
#define QKV_STRIDE 18874368   // 1152*16*64*16
#define ATTN_ELEMS 75497472   // 1152*16*64*64
#define AVG_ELEMS  73728      // 1152*64

__device__ __align__(16) float g_scratch[2 * QKV_STRIDE];   // q then k: [qkv][win][head][n][d]

__device__ __forceinline__ float tf32r(float x) {
    uint32_t u;
    asm("cvt.rna.tf32.f32 %0, %1;" : "=r"(u) : "f"(x));
    return __uint_as_float(u);
}

__device__ __forceinline__ void mma_tf32(float c[4], const uint32_t a[4], const uint32_t b[2]) {
    asm volatile(
        "mma.sync.aligned.m16n8k8.row.col.f32.tf32.tf32.f32 "
        "{%0,%1,%2,%3}, {%4,%5,%6,%7}, {%8,%9}, {%0,%1,%2,%3};"
        : "+f"(c[0]), "+f"(c[1]), "+f"(c[2]), "+f"(c[3])
        : "r"(a[0]), "r"(a[1]), "r"(a[2]), "r"(a[3]), "r"(b[0]), "r"(b[1]));
}

// ---------------- fused 1x1conv(GEMM, tf32 tensor) + BN + ReLU + window rearrange ------
// C[o,p] = sum_c W[o,c] * X[b,c,p]   M=512(o) N=73728(p) K=256
// Block 128x128, 8 warps (2x4), warp 64x32 = 4x4 m16n8k8 frags, K-chunk 32.
__global__ __launch_bounds__(256) void proj_kernel(
    const float* __restrict__ x, const float* __restrict__ w,
    const float* __restrict__ gamma, const float* __restrict__ beta,
    const float* __restrict__ rmean, const float* __restrict__ rvar)
{
    __shared__ __align__(16) float As[128][36];    // [o][k], pad 36
    __shared__ __align__(16) float Bs[32][136];    // [k][p], pad 136
    __shared__ float sinv[128], sbz[128];

    const int tid  = threadIdx.x;
    const int warp = tid >> 5;
    const int lane = tid & 31;
    const int o0   = blockIdx.x * 128;
    const int pg0  = blockIdx.y * 128;
    const int b    = pg0 / HW;               // tile never crosses batch (36864 % 128 == 0)
    const int pp0  = pg0 - b * HW;
    const float* xb = x + (size_t)b * (Cc * HW);

    if (tid < 128) {
        int og = o0 + tid;
        float iv = gamma[og] * rsqrtf(rvar[og] + 1e-5f);
        sinv[tid] = iv;
        sbz[tid]  = beta[og] - rmean[og] * iv;
    }

    const int wm = (warp >> 2) * 64;
    const int wn = (warp & 3) * 32;

    float acc[4][4][4];
#pragma unroll
    for (int mi = 0; mi < 4; mi++)
#pragma unroll
        for (int ni = 0; ni < 4; ni++)
#pragma unroll
            for (int r = 0; r < 4; r++) acc[mi][ni][r] = 0.f;

    for (int c0 = 0; c0 < Cc; c0 += 32) {
        __syncthreads();
        // A tile: 128 o x 32 k. coalesced LDG (8 lanes = 128B row chunk), STS.128.
#pragma unroll
        for (int l = 0; l < 4; l++) {
            int idx = tid + l * 256;
            int o = idx >> 3, cg = idx & 7;
            float4 v = *reinterpret_cast<const float4*>(&w[(o0 + o) * Cc + c0 + cg * 4]);
            v.x = tf32r(v.x); v.y = tf32r(v.y); v.z = tf32r(v.z); v.w = tf32r(v.w);
            *reinterpret_cast<float4*>(&As[o][cg * 4]) = v;
        }
        // B tile: 32 k x 128 p. rows contiguous in p.
#pragma unroll
        for (int l = 0; l < 4; l++) {
            int idx = tid + l * 256;
            int r = idx >> 5, c4 = idx & 31;
            float4 v = *reinterpret_cast<const float4*>(&xb[(c0 + r) * HW + pp0 + c4 * 4]);
            v.x = tf32r(v.x); v.y = tf32r(v.y); v.z = tf32r(v.z); v.w = tf32r(v.w);
            *reinterpret_cast<float4*>(&Bs[r][c4 * 4]) = v;
        }
        __syncthreads();

#pragma unroll
        for (int kk = 0; kk < 4; kk++) {
            const int k8 = kk * 8;
            uint32_t a[4][4], bf[4][2];
            const int kq = k8 + (lane & 3);
#pragma unroll
            for (int mi = 0; mi < 4; mi++) {
                int m = wm + mi * 16 + (lane >> 2);
                a[mi][0] = __float_as_uint(As[m][kq]);
                a[mi][1] = __float_as_uint(As[m + 8][kq]);
                a[mi][2] = __float_as_uint(As[m][kq + 4]);
                a[mi][3] = __float_as_uint(As[m + 8][kq + 4]);
            }
#pragma unroll
            for (int ni = 0; ni < 4; ni++) {
                int p = wn + ni * 8 + (lane >> 2);
                bf[ni][0] = __float_as_uint(Bs[kq][p]);
                bf[ni][1] = __float_as_uint(Bs[kq + 4][p]);
            }
#pragma unroll
            for (int mi = 0; mi < 4; mi++)
#pragma unroll
                for (int ni = 0; ni < 4; ni++)
                    mma_tf32(acc[mi][ni], a[mi], bf[ni]);
        }
    }

    // epilogue: BN + ReLU + scatter to [qkv][win][head][n][d]
    int winv[4][2], nn[4][2];
#pragma unroll
    for (int ni = 0; ni < 4; ni++)
#pragma unroll
        for (int e = 0; e < 2; e++) {
            int pin = pp0 + wn + ni * 8 + 2 * (lane & 3) + e;
            int row = pin / 192;
            int col = pin - row * 192;
            winv[ni][e] = b * 576 + (row >> 3) * 24 + (col >> 3);
            nn[ni][e]   = ((row & 7) << 3) + (col & 7);
        }
#pragma unroll
    for (int mi = 0; mi < 4; mi++) {
#pragma unroll
        for (int rh = 0; rh < 2; rh++) {
            int ol = wm + mi * 16 + (lane >> 2) + rh * 8;
            int o  = o0 + ol;
            float iv = sinv[ol], bz = sbz[ol];
            int qkv  = o >> 8;
            int head = (o >> 4) & 15;
            int d    = o & 15;
            float* basep = g_scratch + (size_t)qkv * QKV_STRIDE + head * 1024 + d;
#pragma unroll
            for (int ni = 0; ni < 4; ni++)
#pragma unroll
                for (int e = 0; e < 2; e++) {
                    float t = acc[mi][ni][rh * 2 + e] * iv + bz;
                    basep[winv[ni][e] * 16384 + nn[ni][e] * 16] = t > 0.f ? t : 0.f;
                }
        }
    }
}

// ---------------- attention: 4 (win,head) units per block, 64 thr/unit, 8x8 microtile ----
__global__ __launch_bounds__(256) void attn_kernel(
    const float* __restrict__ rel_table,
    float* __restrict__ out_attn, float* __restrict__ out_avg)
{
    __shared__ __align__(16) float qt[4][1024];   // [unit][d*64 + n]
    __shared__ __align__(16) float kt[4][1024];   // [unit][d*64 + m]
    __shared__ float biasu[4][226];

    const int tid  = threadIdx.x;
    const int u    = tid >> 6;
    const int t    = tid & 63;
    const int gu   = blockIdx.x * 4 + u;
    const int head = gu & 15;
    const int win  = gu >> 4;

    const float* qg = g_scratch + (size_t)win * 16384 + head * 1024;
    const float* kg = qg + QKV_STRIDE;

#pragma unroll
    for (int d4 = 0; d4 < 4; d4++) {
        float4 v = *reinterpret_cast<const float4*>(&qg[t*16 + d4*4]);
        qt[u][(d4*4+0)*64 + t] = v.x;
        qt[u][(d4*4+1)*64 + t] = v.y;
        qt[u][(d4*4+2)*64 + t] = v.z;
        qt[u][(d4*4+3)*64 + t] = v.w;
        float4 kv = *reinterpret_cast<const float4*>(&kg[t*16 + d4*4]);
        kt[u][(d4*4+0)*64 + t] = kv.x;
        kt[u][(d4*4+1)*64 + t] = kv.y;
        kt[u][(d4*4+2)*64 + t] = kv.z;
        kt[u][(d4*4+3)*64 + t] = kv.w;
    }
    for (int idx = t; idx < 225; idx += 64)
        biasu[u][idx] = rel_table[idx * 16 + head];
    __syncthreads();

    const int cc = t & 7;
    const int rr = t >> 3;

    float acc[8][8];
#pragma unroll
    for (int i = 0; i < 8; i++)
#pragma unroll
        for (int j = 0; j < 8; j++) acc[i][j] = 0.f;

    const float* qb = &qt[u][rr * 8];
    const float* kb = &kt[u][cc * 8];
#pragma unroll
    for (int d = 0; d < 16; d++) {
        float a[8], bb[8];
        *reinterpret_cast<float4*>(&a[0])  = *reinterpret_cast<const float4*>(&qb[d*64]);
        *reinterpret_cast<float4*>(&a[4])  = *reinterpret_cast<const float4*>(&qb[d*64 + 4]);
        *reinterpret_cast<float4*>(&bb[0]) = *reinterpret_cast<const float4*>(&kb[d*64]);
        *reinterpret_cast<float4*>(&bb[4]) = *reinterpret_cast<const float4*>(&kb[d*64 + 4]);
#pragma unroll
        for (int i = 0; i < 8; i++)
#pragma unroll
            for (int j = 0; j < 8; j++)
                acc[i][j] += a[i] * bb[j];
    }

    float b[15];
    {
        const float* bp = &biasu[u][(rr - cc + 7) * 15];
#pragma unroll
        for (int k = 0; k < 15; k++) b[k] = bp[k];
    }
#pragma unroll
    for (int i = 0; i < 8; i++)
#pragma unroll
        for (int j = 0; j < 8; j++)
            acc[i][j] = acc[i][j] * 0.25f + b[i - j + 7];

#pragma unroll
    for (int j = 0; j < 8; j++) {
        float s = acc[0][j] + acc[1][j] + acc[2][j] + acc[3][j]
                + acc[4][j] + acc[5][j] + acc[6][j] + acc[7][j];
        s += __shfl_xor_sync(0xffffffffu, s, 8);
        s += __shfl_xor_sync(0xffffffffu, s, 16);
        if ((t & 31) < 8)
            atomicAdd(&out_avg[win * 64 + cc * 8 + j], s * (1.0f / 1024.0f));
    }

#pragma unroll
    for (int i = 0; i < 8; i++) {
        float mx = acc[i][0];
#pragma unroll
        for (int j = 1; j < 8; j++) mx = fmaxf(mx, acc[i][j]);
        mx = fmaxf(mx, __shfl_xor_sync(0xffffffffu, mx, 1));
        mx = fmaxf(mx, __shfl_xor_sync(0xffffffffu, mx, 2));
        mx = fmaxf(mx, __shfl_xor_sync(0xffffffffu, mx, 4));
        float sum = 0.f;
#pragma unroll
        for (int j = 0; j < 8; j++) { acc[i][j] = __expf(acc[i][j] - mx); sum += acc[i][j]; }
        sum += __shfl_xor_sync(0xffffffffu, sum, 1);
        sum += __shfl_xor_sync(0xffffffffu, sum, 2);
        sum += __shfl_xor_sync(0xffffffffu, sum, 4);
        float rinv = __frcp_rn(sum);
#pragma unroll
        for (int j = 0; j < 8; j++) acc[i][j] *= rinv;
    }

    float* ob = out_attn + ((size_t)(win * 16 + head) * 64 + rr * 8) * 64 + cc * 8;
#pragma unroll
    for (int i = 0; i < 8; i++) {
        float4 v0 = make_float4(acc[i][0], acc[i][1], acc[i][2], acc[i][3]);
        float4 v1 = make_float4(acc[i][4], acc[i][5], acc[i][6], acc[i][7]);
        *reinterpret_cast<float4*>(&ob[i * 64])     = v0;
        *reinterpret_cast<float4*>(&ob[i * 64 + 4]) = v1;
    }
}

extern "C" void kernel_launch(void* const* d_in, const int* in_sizes, int n_in,
                              void* d_out, int out_size) {
    const float* x     = (const float*)d_in[0];
    const float* w     = (const float*)d_in[1];
    const float* gamma = (const float*)d_in[2];
    const float* beta  = (const float*)d_in[3];
    const float* rmean = (const float*)d_in[4];
    const float* rvar  = (const float*)d_in[5];
    const float* rel   = (const float*)d_in[6];
    float* out     = (float*)d_out;
    float* out_avg = out + ATTN_ELEMS;

    cudaMemsetAsync(out_avg, 0, AVG_ELEMS * sizeof(float));
    proj_kernel<<<dim3(4, 576), 256>>>(x, w, gamma, beta, rmean, rvar);
    attn_kernel<<<4608, 256>>>(rel, out, out_avg);
}